// round 16
// baseline (speedup 1.0000x reference)
#include <cuda_runtime.h>
#include <cuda_fp16.h>
#include <cstdint>

#define L_DIM 1024
#define N_DIM 4096
#define K_DIM 1024
#define NHEADS 4
#define NSCHUNK 8

// ---------------- scratch (device globals; no allocs allowed) ----------------
__device__ __half g_qh[L_DIM * N_DIM];
__device__ __half g_keysh[NHEADS * L_DIM * N_DIM];
__device__ float  g_partial[NHEADS * NSCHUNK * N_DIM];
__device__ float  g_weight[NHEADS * N_DIM];
__device__ __half g_fusedh[L_DIM * N_DIM];
__device__ int    g_qflag[256];                         // q tile completion flags

__device__ __half g_WL[L_DIM * K_DIM];
__device__ __half g_Wimg[NHEADS * L_DIM * K_DIM];
__device__ __half g_Wf[L_DIM * K_DIM];
__device__ __half g_P16[K_DIM * N_DIM];
__device__ __half g_I16[K_DIM * N_DIM];

// ---------------- PTX helpers (sm_80-portable only) ----------------
__device__ __forceinline__ uint32_t smem_u32(const void* p) {
    uint32_t r;
    asm("{ .reg .u64 t; cvta.to.shared.u64 t, %1; cvt.u32.u64 %0, t; }" : "=r"(r) : "l"(p));
    return r;
}
__device__ __forceinline__ void cp16(uint32_t dst, const void* src) {
    asm volatile("cp.async.cg.shared.global [%0], [%1], 16;" :: "r"(dst), "l"(src) : "memory");
}
__device__ __forceinline__ void cp_commit() {
    asm volatile("cp.async.commit_group;" ::: "memory");
}
__device__ __forceinline__ void cp_wait1() {
    asm volatile("cp.async.wait_group 1;" ::: "memory");
}
__device__ __forceinline__ void cp_wait0() {
    asm volatile("cp.async.wait_group 0;" ::: "memory");
}
__device__ __forceinline__ void ldsm_x4(uint32_t& r0, uint32_t& r1, uint32_t& r2, uint32_t& r3,
                                        uint32_t addr) {
    asm volatile("ldmatrix.sync.aligned.m8n8.x4.shared.b16 {%0,%1,%2,%3}, [%4];"
                 : "=r"(r0), "=r"(r1), "=r"(r2), "=r"(r3) : "r"(addr));
}
__device__ __forceinline__ void ldsm_x4_trans(uint32_t& r0, uint32_t& r1, uint32_t& r2, uint32_t& r3,
                                              uint32_t addr) {
    asm volatile("ldmatrix.sync.aligned.m8n8.x4.trans.shared.b16 {%0,%1,%2,%3}, [%4];"
                 : "=r"(r0), "=r"(r1), "=r"(r2), "=r"(r3) : "r"(addr));
}
__device__ __forceinline__ void mma_f16(float* c, const uint32_t* a, uint32_t b0, uint32_t b1) {
    asm volatile(
        "mma.sync.aligned.m16n8k16.row.col.f32.f16.f16.f32 "
        "{%0,%1,%2,%3}, {%4,%5,%6,%7}, {%8,%9}, {%0,%1,%2,%3};"
        : "+f"(c[0]), "+f"(c[1]), "+f"(c[2]), "+f"(c[3])
        : "r"(a[0]), "r"(a[1]), "r"(a[2]), "r"(a[3]), "r"(b0), "r"(b1));
}

// ---------------- fp16 mma.sync GEMM: A [m,k] k-major, B [k,n] n-major ----------------
#define GBM 128
#define GBN 128
#define GBK 64
#define OFF_A 0
#define OFF_B 16384
#define STAGE_B 32768
#define NSTAGE 3
#define GEMM_DSMEM (NSTAGE * STAGE_B)   // 96 KB -> 2 CTAs/SM
#define KSTAGES (K_DIM / GBK)           // 16

template <bool SCORE, bool PRODUCE, typename OT>
__device__ __forceinline__ void gemm_body(
    const __half* __restrict__ A, const __half* __restrict__ B,
    const float* __restrict__ bias, OT* __restrict__ C,
    int bm, int bn,
    const __half* __restrict__ qbuf, float* __restrict__ partial, int chunk_idx,
    int* qflag, int flag_idx)
{
    extern __shared__ char sm_raw[];
    const uint32_t sbase = smem_u32(sm_raw);

    const int tid  = threadIdx.x;
    const int lane = tid & 31;
    const int wid  = tid >> 5;
    const int wm   = wid >> 1;
    const int wn   = wid & 1;

    int arow[4], acol[4], brow[4], bcol[4];
    uint32_t adst[4], bdst[4];
    #pragma unroll
    for (int t = 0; t < 4; t++) {
        int idx = (t << 8) + tid;
        int ra = idx >> 3, ca = idx & 7;
        arow[t] = ra; acol[t] = ca;
        adst[t] = (uint32_t)((ra << 7) + ((ca ^ (ra & 7)) << 4));
        int rb = idx >> 4, cb = idx & 15;
        brow[t] = rb; bcol[t] = cb;
        bdst[t] = (uint32_t)((rb << 8) + ((cb ^ (rb & 7)) << 4));
    }

    auto issue_stage = [&](int kstage, int buf) {
        const uint32_t sb = sbase + buf * STAGE_B;
        const int k0 = kstage * GBK;
        #pragma unroll
        for (int t = 0; t < 4; t++) {
            cp16(sb + OFF_A + adst[t],
                 A + (size_t)(bm + arow[t]) * K_DIM + k0 + (acol[t] << 3));
            cp16(sb + OFF_B + bdst[t],
                 B + (size_t)(k0 + brow[t]) * N_DIM + bn + (bcol[t] << 3));
        }
    };

    float acc[2][8][4];
    #pragma unroll
    for (int m = 0; m < 2; m++)
        #pragma unroll
        for (int n = 0; n < 8; n++)
            #pragma unroll
            for (int v = 0; v < 4; v++)
                acc[m][n][v] = 0.0f;

    const int a_row0 = wm * 32 + (lane & 15);
    const int a_ch0  = lane >> 4;
    const int b_krow0 = (lane & 7) + (((lane >> 3) & 1) << 3);
    const int b_nch0  = wn * 8 + (lane >> 4);

    issue_stage(0, 0); cp_commit();
    issue_stage(1, 1); cp_commit();

    int bc = 0;
    for (int i = 0; i < KSTAGES; i++) {
        if (i < KSTAGES - 1) cp_wait1(); else cp_wait0();
        __syncthreads();

        if (i + 2 < KSTAGES) {
            int bi = bc + 2; if (bi >= NSTAGE) bi -= NSTAGE;
            issue_stage(i + 2, bi);
            cp_commit();
        }

        const uint32_t st = sbase + bc * STAGE_B;
        #pragma unroll
        for (int ks = 0; ks < 4; ks++) {
            uint32_t ah[2][4], bh[4][4];
            #pragma unroll
            for (int mt = 0; mt < 2; mt++) {
                const int r = a_row0 + mt * 16;
                const int ch = ks * 2 + a_ch0;
                ldsm_x4(ah[mt][0], ah[mt][1], ah[mt][2], ah[mt][3],
                        st + OFF_A + (r << 7) + ((ch ^ (r & 7)) << 4));
            }
            #pragma unroll
            for (int np = 0; np < 4; np++) {
                const int r = ks * 16 + b_krow0;
                const int nc = b_nch0 + np * 2;
                ldsm_x4_trans(bh[np][0], bh[np][1], bh[np][2], bh[np][3],
                              st + OFF_B + (r << 8) + ((nc ^ (r & 7)) << 4));
            }
            #pragma unroll
            for (int mt = 0; mt < 2; mt++)
                #pragma unroll
                for (int np = 0; np < 4; np++) {
                    mma_f16(acc[mt][np * 2 + 0], ah[mt], bh[np][0], bh[np][1]);
                    mma_f16(acc[mt][np * 2 + 1], ah[mt], bh[np][2], bh[np][3]);
                }
        }
        bc = (bc + 1 == NSTAGE) ? 0 : bc + 1;
    }

    // SCORE path: wait for the q tile this block's epilogue reads
    if (SCORE) {
        if (tid == 0) {
            volatile int* f = (volatile int*)&qflag[flag_idx];
            while (*f == 0) { }
            __threadfence();
        }
        __syncthreads();
    }

    float s[16];
    if (SCORE) {
        #pragma unroll
        for (int j = 0; j < 16; j++) s[j] = 0.0f;
    }

    #pragma unroll
    for (int mt = 0; mt < 2; mt++) {
        const int row = bm + wm * 32 + mt * 16 + (lane >> 2);
        const float bv0 = bias[row], bv8 = bias[row + 8];
        const int c0 = row & (L_DIM - 1);
        #pragma unroll
        for (int nt = 0; nt < 8; nt++) {
            const int col = bn + wn * 64 + nt * 8 + (lane & 3) * 2;
            const float k00 = acc[mt][nt][0] + bv0, k01 = acc[mt][nt][1] + bv0;
            const float k80 = acc[mt][nt][2] + bv8, k81 = acc[mt][nt][3] + bv8;
            if (sizeof(OT) == 2) {
                *reinterpret_cast<__half2*>(
                    (__half*)C + (size_t)row * N_DIM + col) = __floats2half2_rn(k00, k01);
                *reinterpret_cast<__half2*>(
                    (__half*)C + (size_t)(row + 8) * N_DIM + col) = __floats2half2_rn(k80, k81);
            } else {
                *reinterpret_cast<float2*>(
                    (float*)C + (size_t)row * N_DIM + col) = make_float2(k00, k01);
                *reinterpret_cast<float2*>(
                    (float*)C + (size_t)(row + 8) * N_DIM + col) = make_float2(k80, k81);
            }
            if (SCORE) {
                const float2 q0 = __half22float2(*reinterpret_cast<const __half2*>(
                    &qbuf[(size_t)c0 * N_DIM + col]));
                const float2 q8 = __half22float2(*reinterpret_cast<const __half2*>(
                    &qbuf[(size_t)(c0 + 8) * N_DIM + col]));
                s[nt * 2 + 0] += k00 * q0.x + k80 * q8.x;
                s[nt * 2 + 1] += k01 * q0.y + k81 * q8.y;
            }
        }
    }

    if (PRODUCE) {
        __syncthreads();                     // all q stores issued
        if (tid == 0) {
            __threadfence();                 // publish
            atomicExch(&qflag[flag_idx], 1);
        }
    }

    if (SCORE) {
        #pragma unroll
        for (int j = 0; j < 16; j++) {
            s[j] += __shfl_xor_sync(0xffffffffu, s[j], 4);
            s[j] += __shfl_xor_sync(0xffffffffu, s[j], 8);
            s[j] += __shfl_xor_sync(0xffffffffu, s[j], 16);
        }
        __syncthreads();
        float* sbuf = reinterpret_cast<float*>(sm_raw);
        if ((lane >> 2) == 0) {
            #pragma unroll
            for (int nt = 0; nt < 8; nt++) {
                const int lc = wn * 64 + nt * 8 + (lane & 3) * 2;
                sbuf[wid * 128 + lc + 0] = s[nt * 2 + 0];
                sbuf[wid * 128 + lc + 1] = s[nt * 2 + 1];
            }
        }
        __syncthreads();
        if (tid < 128) {
            const int wn_ = tid >> 6;
            float tot = sbuf[(0 * 2 + wn_) * 128 + tid]
                      + sbuf[(1 * 2 + wn_) * 128 + tid]
                      + sbuf[(2 * 2 + wn_) * 128 + tid]
                      + sbuf[(3 * 2 + wn_) * 128 + tid];
            partial[(size_t)chunk_idx * N_DIM + bn + tid] = tot;
        }
    }
}

// merged q + keys: by 0-7 -> q (produce flags), by 8-39 -> keys (consume flags)
__global__ __launch_bounds__(256, 2) void gemm_qkeys(
    const __half* __restrict__ WL, const __half* __restrict__ P16,
    const float* __restrict__ b_L, __half* __restrict__ qh,
    const __half* __restrict__ WI, const __half* __restrict__ I16,
    const float* __restrict__ b_img, __half* __restrict__ keysh,
    float* __restrict__ partial, int* __restrict__ qflag)
{
    const int by = blockIdx.y;
    const int bx = blockIdx.x;
    if (by < 8) {
        gemm_body<false, true, __half>(WL, P16, b_L, qh, by * GBM, bx * GBN,
                                       nullptr, nullptr, 0, qflag, by * 32 + bx);
    } else {
        const int chunk = by - 8;
        gemm_body<true, false, __half>(WI, I16, b_img, keysh, chunk * GBM, bx * GBN,
                                       qh, partial, chunk,
                                       qflag, (chunk & 7) * 32 + bx);
    }
}

__global__ __launch_bounds__(256, 2) void gemm_f(
    const __half* __restrict__ WF, const __half* __restrict__ F16,
    const float* __restrict__ bias, float* __restrict__ C)
{
    gemm_body<false, false, float>(WF, F16, bias, C, blockIdx.y * GBM, blockIdx.x * GBN,
                                   nullptr, nullptr, 0, nullptr, 0);
}

// ---------------- single fused fp32->fp16 convert + flag reset ----------------
__global__ __launch_bounds__(256) void convert_all(
    const float* __restrict__ W_L, const float* __restrict__ W_img,
    const float* __restrict__ W_f, const float* __restrict__ point,
    const float* __restrict__ img,
    __half* __restrict__ WL, __half* __restrict__ WI, __half* __restrict__ WF,
    __half* __restrict__ P16, __half* __restrict__ I16, int* __restrict__ qflag)
{
    if (blockIdx.x == 0) qflag[threadIdx.x] = 0;        // reset 256 flags each replay
    const size_t WSZ = (size_t)L_DIM * K_DIM;
    const size_t ASZ = (size_t)K_DIM * N_DIM;
    size_t i = ((size_t)blockIdx.x * 256 + threadIdx.x) * 4;
    const float* src; __half* dst; size_t off;
    if (i < WSZ)                    { src = W_L;   dst = WL;  off = i; }
    else if (i < 5 * WSZ)           { src = W_img; dst = WI;  off = i - WSZ; }
    else if (i < 6 * WSZ)           { src = W_f;   dst = WF;  off = i - 5 * WSZ; }
    else if (i < 6 * WSZ + ASZ)     { src = point; dst = P16; off = i - 6 * WSZ; }
    else                            { src = img;   dst = I16; off = i - 6 * WSZ - ASZ; }
    float4 v = *reinterpret_cast<const float4*>(src + off);
    __half2* d = reinterpret_cast<__half2*>(dst + off);
    d[0] = __floats2half2_rn(v.x, v.y);
    d[1] = __floats2half2_rn(v.z, v.w);
}

// ---------------- softmax over heads ----------------
__global__ __launch_bounds__(256) void softmax_heads(
    const float* __restrict__ partial, float* __restrict__ weight,
    float* __restrict__ wmap_out)
{
    int n = blockIdx.x * 256 + threadIdx.x;
    float s[NHEADS] = {0.f, 0.f, 0.f, 0.f};
    #pragma unroll
    for (int h = 0; h < NHEADS; h++)
        #pragma unroll
        for (int j = 0; j < NSCHUNK; j++)
            s[h] += partial[((size_t)(h * NSCHUNK + j)) * N_DIM + n];
    const float inv_sqrt_dk = 1.0f / 32.0f;
    float m = -1e30f;
    #pragma unroll
    for (int h = 0; h < NHEADS; h++) { s[h] *= inv_sqrt_dk; m = fmaxf(m, s[h]); }
    float e[NHEADS], sum = 0.f;
    #pragma unroll
    for (int h = 0; h < NHEADS; h++) { e[h] = __expf(s[h] - m); sum += e[h]; }
    float inv = 1.0f / sum;
    #pragma unroll
    for (int h = 0; h < NHEADS; h++) {
        float wv = e[h] * inv;
        weight[(size_t)h * N_DIM + n]   = wv;
        wmap_out[(size_t)h * N_DIM + n] = wv;
    }
}

// ---------------- z + residual + LayerNorm ----------------
__global__ __launch_bounds__(512) void z_layernorm(
    const __half* __restrict__ keysh, const __half* __restrict__ qh,
    const float* __restrict__ weight, const float* __restrict__ gamma,
    const float* __restrict__ beta, __half* __restrict__ fusedh)
{
    const int c = blockIdx.x;
    __shared__ float r1[16], r2[16];
    __shared__ float s_mean, s_rstd;

    float v[2][4];
    float lsum = 0.f, lsq = 0.f;
    #pragma unroll
    for (int j = 0; j < 2; j++) {
        const int n4 = (j * 512 + threadIdx.x) * 4;
        const __half2* qa = reinterpret_cast<const __half2*>(&qh[(size_t)c * N_DIM + n4]);
        float2 q0 = __half22float2(qa[0]);
        float2 q1 = __half22float2(qa[1]);
        v[j][0] = q0.x; v[j][1] = q0.y; v[j][2] = q1.x; v[j][3] = q1.y;
        #pragma unroll
        for (int h = 0; h < NHEADS; h++) {
            const __half2* kh = reinterpret_cast<const __half2*>(
                &keysh[((size_t)(h * L_DIM + c)) * N_DIM + n4]);
            float2 ka = __half22float2(kh[0]);
            float2 kb = __half22float2(kh[1]);
            float4 wv = *reinterpret_cast<const float4*>(&weight[(size_t)h * N_DIM + n4]);
            v[j][0] += wv.x * ka.x; v[j][1] += wv.y * ka.y;
            v[j][2] += wv.z * kb.x; v[j][3] += wv.w * kb.y;
        }
        #pragma unroll
        for (int e = 0; e < 4; e++) { lsum += v[j][e]; lsq += v[j][e] * v[j][e]; }
    }
    #pragma unroll
    for (int o = 16; o > 0; o >>= 1) {
        lsum += __shfl_xor_sync(0xffffffffu, lsum, o);
        lsq  += __shfl_xor_sync(0xffffffffu, lsq, o);
    }
    const int wid = threadIdx.x >> 5, lid = threadIdx.x & 31;
    if (lid == 0) { r1[wid] = lsum; r2[wid] = lsq; }
    __syncthreads();
    if (threadIdx.x == 0) {
        float ts = 0.f, tq = 0.f;
        #pragma unroll
        for (int i = 0; i < 16; i++) { ts += r1[i]; tq += r2[i]; }
        float mean = ts * (1.0f / N_DIM);
        float var  = tq * (1.0f / N_DIM) - mean * mean;
        s_mean = mean;
        s_rstd = rsqrtf(var + 1e-5f);
    }
    __syncthreads();
    const float mean = s_mean, rstd = s_rstd;
    #pragma unroll
    for (int j = 0; j < 2; j++) {
        const int n4 = (j * 512 + threadIdx.x) * 4;
        float4 ga = *reinterpret_cast<const float4*>(&gamma[n4]);
        float4 ba = *reinterpret_cast<const float4*>(&beta[n4]);
        float o0 = (v[j][0] - mean) * rstd * ga.x + ba.x;
        float o1 = (v[j][1] - mean) * rstd * ga.y + ba.y;
        float o2 = (v[j][2] - mean) * rstd * ga.z + ba.z;
        float o3 = (v[j][3] - mean) * rstd * ga.w + ba.w;
        __half2* dst = reinterpret_cast<__half2*>(&fusedh[(size_t)c * N_DIM + n4]);
        dst[0] = __floats2half2_rn(o0, o1);
        dst[1] = __floats2half2_rn(o2, o3);
    }
}

// ---------------- launch ----------------
extern "C" void kernel_launch(void* const* d_in, const int* in_sizes, int n_in,
                              void* d_out, int out_size)
{
    const float* point = (const float*)d_in[0];
    const float* img   = (const float*)d_in[1];
    const float* W_img = (const float*)d_in[2];
    const float* b_img = (const float*)d_in[3];
    const float* W_L   = (const float*)d_in[4];
    const float* b_L   = (const float*)d_in[5];
    const float* ln_g  = (const float*)d_in[6];
    const float* ln_b  = (const float*)d_in[7];
    const float* W_f   = (const float*)d_in[8];
    const float* b_f   = (const float*)d_in[9];

    float* out  = (float*)d_out;
    float* wmap = out + (size_t)L_DIM * N_DIM;

    float *partial, *weight;
    __half *qh, *keysh, *fusedh;
    int* qflag;
    cudaGetSymbolAddress((void**)&qh,      g_qh);
    cudaGetSymbolAddress((void**)&keysh,   g_keysh);
    cudaGetSymbolAddress((void**)&partial, g_partial);
    cudaGetSymbolAddress((void**)&weight,  g_weight);
    cudaGetSymbolAddress((void**)&fusedh,  g_fusedh);
    cudaGetSymbolAddress((void**)&qflag,   g_qflag);

    __half *WL, *WI, *WF, *P16, *I16;
    cudaGetSymbolAddress((void**)&WL, g_WL);
    cudaGetSymbolAddress((void**)&WI, g_Wimg);
    cudaGetSymbolAddress((void**)&WF, g_Wf);
    cudaGetSymbolAddress((void**)&P16, g_P16);
    cudaGetSymbolAddress((void**)&I16, g_I16);

    cudaFuncSetAttribute(gemm_qkeys, cudaFuncAttributeMaxDynamicSharedMemorySize, GEMM_DSMEM);
    cudaFuncSetAttribute(gemm_f,     cudaFuncAttributeMaxDynamicSharedMemorySize, GEMM_DSMEM);

    convert_all<<<(14 * 1024 * 1024) / 1024, 256>>>(
        W_L, W_img, W_f, point, img, WL, WI, WF, P16, I16, qflag);

    // q (by 0-7, dispatched first) + keys (by 8-39) in one launch, flag handshake
    gemm_qkeys<<<dim3(N_DIM / GBN, 8 + 32), 256, GEMM_DSMEM>>>(
        WL, P16, b_L, qh, WI, I16, b_img, keysh, partial, qflag);

    softmax_heads<<<N_DIM / 256, 256>>>(partial, weight, wmap);
    z_layernorm<<<L_DIM, 512>>>(keysh, qh, weight, ln_g, ln_b, fusedh);

    gemm_f<<<dim3(N_DIM / GBN, L_DIM / GBM), 256, GEMM_DSMEM>>>(WF, fusedh, b_f, out);
}

// round 17
// speedup vs baseline: 1.0138x; 1.0138x over previous
#include <cuda_runtime.h>
#include <cuda_fp16.h>
#include <cstdint>

#define L_DIM 1024
#define N_DIM 4096
#define K_DIM 1024
#define NHEADS 4
#define NSCHUNK 8

// ---------------- scratch (device globals; no allocs allowed) ----------------
__device__ __half g_qh[L_DIM * N_DIM];
__device__ __half g_keysh[NHEADS * L_DIM * N_DIM];
__device__ float  g_partial[NHEADS * NSCHUNK * N_DIM];
__device__ float  g_weight[NHEADS * N_DIM];
__device__ __half g_fusedh[L_DIM * N_DIM];

__device__ __half g_WL[L_DIM * K_DIM];
__device__ __half g_Wimg[NHEADS * L_DIM * K_DIM];
__device__ __half g_Wf[L_DIM * K_DIM];
__device__ __half g_P16[K_DIM * N_DIM];
__device__ __half g_I16[K_DIM * N_DIM];

// ---------------- PTX helpers (sm_80-portable only) ----------------
__device__ __forceinline__ uint32_t smem_u32(const void* p) {
    uint32_t r;
    asm("{ .reg .u64 t; cvta.to.shared.u64 t, %1; cvt.u32.u64 %0, t; }" : "=r"(r) : "l"(p));
    return r;
}
__device__ __forceinline__ void cp16(uint32_t dst, const void* src) {
    asm volatile("cp.async.cg.shared.global [%0], [%1], 16;" :: "r"(dst), "l"(src) : "memory");
}
__device__ __forceinline__ void cp_commit() {
    asm volatile("cp.async.commit_group;" ::: "memory");
}
__device__ __forceinline__ void cp_wait1() {
    asm volatile("cp.async.wait_group 1;" ::: "memory");
}
__device__ __forceinline__ void cp_wait0() {
    asm volatile("cp.async.wait_group 0;" ::: "memory");
}
__device__ __forceinline__ void ldsm_x4(uint32_t& r0, uint32_t& r1, uint32_t& r2, uint32_t& r3,
                                        uint32_t addr) {
    asm volatile("ldmatrix.sync.aligned.m8n8.x4.shared.b16 {%0,%1,%2,%3}, [%4];"
                 : "=r"(r0), "=r"(r1), "=r"(r2), "=r"(r3) : "r"(addr));
}
__device__ __forceinline__ void ldsm_x4_trans(uint32_t& r0, uint32_t& r1, uint32_t& r2, uint32_t& r3,
                                              uint32_t addr) {
    asm volatile("ldmatrix.sync.aligned.m8n8.x4.trans.shared.b16 {%0,%1,%2,%3}, [%4];"
                 : "=r"(r0), "=r"(r1), "=r"(r2), "=r"(r3) : "r"(addr));
}
__device__ __forceinline__ void mma_f16(float* c, const uint32_t* a, uint32_t b0, uint32_t b1) {
    asm volatile(
        "mma.sync.aligned.m16n8k16.row.col.f32.f16.f16.f32 "
        "{%0,%1,%2,%3}, {%4,%5,%6,%7}, {%8,%9}, {%0,%1,%2,%3};"
        : "+f"(c[0]), "+f"(c[1]), "+f"(c[2]), "+f"(c[3])
        : "r"(a[0]), "r"(a[1]), "r"(a[2]), "r"(a[3]), "r"(b0), "r"(b1));
}

// ---------------- fp16 mma.sync GEMM: A [m,k] k-major, B [k,n] n-major ----------------
#define GBM 128
#define GBN 128
#define GBK 64
#define OFF_A 0
#define OFF_B 16384
#define STAGE_B 32768
#define NSTAGE 3
#define GEMM_DSMEM (NSTAGE * STAGE_B)   // 96 KB -> 2 CTAs/SM
#define KSTAGES (K_DIM / GBK)           // 16

template <bool SCORE, typename OT>
__device__ __forceinline__ void gemm_body(
    const __half* __restrict__ A, const __half* __restrict__ B,
    const float* __restrict__ bias, OT* __restrict__ C,
    int bm, int bn,
    const __half* __restrict__ qbuf, float* __restrict__ partial, int chunk_idx)
{
    extern __shared__ char sm_raw[];
    const uint32_t sbase = smem_u32(sm_raw);

    const int tid  = threadIdx.x;
    const int lane = tid & 31;
    const int wid  = tid >> 5;
    const int wm   = wid >> 1;
    const int wn   = wid & 1;

    int arow[4], acol[4], brow[4], bcol[4];
    uint32_t adst[4], bdst[4];
    #pragma unroll
    for (int t = 0; t < 4; t++) {
        int idx = (t << 8) + tid;
        int ra = idx >> 3, ca = idx & 7;
        arow[t] = ra; acol[t] = ca;
        adst[t] = (uint32_t)((ra << 7) + ((ca ^ (ra & 7)) << 4));
        int rb = idx >> 4, cb = idx & 15;
        brow[t] = rb; bcol[t] = cb;
        bdst[t] = (uint32_t)((rb << 8) + ((cb ^ (rb & 7)) << 4));
    }

    auto issue_stage = [&](int kstage, int buf) {
        const uint32_t sb = sbase + buf * STAGE_B;
        const int k0 = kstage * GBK;
        #pragma unroll
        for (int t = 0; t < 4; t++) {
            cp16(sb + OFF_A + adst[t],
                 A + (size_t)(bm + arow[t]) * K_DIM + k0 + (acol[t] << 3));
            cp16(sb + OFF_B + bdst[t],
                 B + (size_t)(k0 + brow[t]) * N_DIM + bn + (bcol[t] << 3));
        }
    };

    float acc[2][8][4];
    #pragma unroll
    for (int m = 0; m < 2; m++)
        #pragma unroll
        for (int n = 0; n < 8; n++)
            #pragma unroll
            for (int v = 0; v < 4; v++)
                acc[m][n][v] = 0.0f;

    const int a_row0 = wm * 32 + (lane & 15);
    const int a_ch0  = lane >> 4;
    const int b_krow0 = (lane & 7) + (((lane >> 3) & 1) << 3);
    const int b_nch0  = wn * 8 + (lane >> 4);

    issue_stage(0, 0); cp_commit();
    issue_stage(1, 1); cp_commit();

    int bc = 0;
    for (int i = 0; i < KSTAGES; i++) {
        if (i < KSTAGES - 1) cp_wait1(); else cp_wait0();
        __syncthreads();

        if (i + 2 < KSTAGES) {
            int bi = bc + 2; if (bi >= NSTAGE) bi -= NSTAGE;
            issue_stage(i + 2, bi);
            cp_commit();
        }

        const uint32_t st = sbase + bc * STAGE_B;
        #pragma unroll
        for (int ks = 0; ks < 4; ks++) {
            uint32_t ah[2][4], bh[4][4];
            #pragma unroll
            for (int mt = 0; mt < 2; mt++) {
                const int r = a_row0 + mt * 16;
                const int ch = ks * 2 + a_ch0;
                ldsm_x4(ah[mt][0], ah[mt][1], ah[mt][2], ah[mt][3],
                        st + OFF_A + (r << 7) + ((ch ^ (r & 7)) << 4));
            }
            #pragma unroll
            for (int np = 0; np < 4; np++) {
                const int r = ks * 16 + b_krow0;
                const int nc = b_nch0 + np * 2;
                ldsm_x4_trans(bh[np][0], bh[np][1], bh[np][2], bh[np][3],
                              st + OFF_B + (r << 8) + ((nc ^ (r & 7)) << 4));
            }
            #pragma unroll
            for (int mt = 0; mt < 2; mt++)
                #pragma unroll
                for (int np = 0; np < 4; np++) {
                    mma_f16(acc[mt][np * 2 + 0], ah[mt], bh[np][0], bh[np][1]);
                    mma_f16(acc[mt][np * 2 + 1], ah[mt], bh[np][2], bh[np][3]);
                }
        }
        bc = (bc + 1 == NSTAGE) ? 0 : bc + 1;
    }

    float s[16];
    if (SCORE) {
        #pragma unroll
        for (int j = 0; j < 16; j++) s[j] = 0.0f;
    }

    #pragma unroll
    for (int mt = 0; mt < 2; mt++) {
        const int row = bm + wm * 32 + mt * 16 + (lane >> 2);
        const float bv0 = bias[row], bv8 = bias[row + 8];
        const int c0 = row & (L_DIM - 1);
        #pragma unroll
        for (int nt = 0; nt < 8; nt++) {
            const int col = bn + wn * 64 + nt * 8 + (lane & 3) * 2;
            const float k00 = acc[mt][nt][0] + bv0, k01 = acc[mt][nt][1] + bv0;
            const float k80 = acc[mt][nt][2] + bv8, k81 = acc[mt][nt][3] + bv8;
            if (sizeof(OT) == 2) {
                *reinterpret_cast<__half2*>(
                    (__half*)C + (size_t)row * N_DIM + col) = __floats2half2_rn(k00, k01);
                *reinterpret_cast<__half2*>(
                    (__half*)C + (size_t)(row + 8) * N_DIM + col) = __floats2half2_rn(k80, k81);
            } else {
                *reinterpret_cast<float2*>(
                    (float*)C + (size_t)row * N_DIM + col) = make_float2(k00, k01);
                *reinterpret_cast<float2*>(
                    (float*)C + (size_t)(row + 8) * N_DIM + col) = make_float2(k80, k81);
            }
            if (SCORE) {
                const float2 q0 = __half22float2(*reinterpret_cast<const __half2*>(
                    &qbuf[(size_t)c0 * N_DIM + col]));
                const float2 q8 = __half22float2(*reinterpret_cast<const __half2*>(
                    &qbuf[(size_t)(c0 + 8) * N_DIM + col]));
                s[nt * 2 + 0] += k00 * q0.x + k80 * q8.x;
                s[nt * 2 + 1] += k01 * q0.y + k81 * q8.y;
            }
        }
    }

    if (SCORE) {
        #pragma unroll
        for (int j = 0; j < 16; j++) {
            s[j] += __shfl_xor_sync(0xffffffffu, s[j], 4);
            s[j] += __shfl_xor_sync(0xffffffffu, s[j], 8);
            s[j] += __shfl_xor_sync(0xffffffffu, s[j], 16);
        }
        __syncthreads();
        float* sbuf = reinterpret_cast<float*>(sm_raw);
        if ((lane >> 2) == 0) {
            #pragma unroll
            for (int nt = 0; nt < 8; nt++) {
                const int lc = wn * 64 + nt * 8 + (lane & 3) * 2;
                sbuf[wid * 128 + lc + 0] = s[nt * 2 + 0];
                sbuf[wid * 128 + lc + 1] = s[nt * 2 + 1];
            }
        }
        __syncthreads();
        if (tid < 128) {
            const int wn_ = tid >> 6;
            float tot = sbuf[(0 * 2 + wn_) * 128 + tid]
                      + sbuf[(1 * 2 + wn_) * 128 + tid]
                      + sbuf[(2 * 2 + wn_) * 128 + tid]
                      + sbuf[(3 * 2 + wn_) * 128 + tid];
            partial[(size_t)chunk_idx * N_DIM + bn + tid] = tot;
        }
    }
}

__global__ __launch_bounds__(256, 2) void gemm_q(
    const __half* __restrict__ WL, const __half* __restrict__ P16,
    const float* __restrict__ b_L, __half* __restrict__ qh)
{
    gemm_body<false, __half>(WL, P16, b_L, qh, blockIdx.y * GBM, blockIdx.x * GBN,
                             nullptr, nullptr, 0);
}

__global__ __launch_bounds__(256, 2) void gemm_keys(
    const __half* __restrict__ WI, const __half* __restrict__ I16,
    const float* __restrict__ b_img, __half* __restrict__ keysh,
    const __half* __restrict__ qh, float* __restrict__ partial)
{
    gemm_body<true, __half>(WI, I16, b_img, keysh, blockIdx.y * GBM, blockIdx.x * GBN,
                            qh, partial, blockIdx.y);
}

__global__ __launch_bounds__(256, 2) void gemm_f(
    const __half* __restrict__ WF, const __half* __restrict__ F16,
    const float* __restrict__ bias, float* __restrict__ C)
{
    gemm_body<false, float>(WF, F16, bias, C, blockIdx.y * GBM, blockIdx.x * GBN,
                            nullptr, nullptr, 0);
}

// ---------------- single fused fp32->fp16 convert ----------------
__global__ __launch_bounds__(256) void convert_all(
    const float* __restrict__ W_L, const float* __restrict__ W_img,
    const float* __restrict__ W_f, const float* __restrict__ point,
    const float* __restrict__ img,
    __half* __restrict__ WL, __half* __restrict__ WI, __half* __restrict__ WF,
    __half* __restrict__ P16, __half* __restrict__ I16)
{
    const size_t WSZ = (size_t)L_DIM * K_DIM;
    const size_t ASZ = (size_t)K_DIM * N_DIM;
    size_t i = ((size_t)blockIdx.x * 256 + threadIdx.x) * 4;
    const float* src; __half* dst; size_t off;
    if (i < WSZ)                    { src = W_L;   dst = WL;  off = i; }
    else if (i < 5 * WSZ)           { src = W_img; dst = WI;  off = i - WSZ; }
    else if (i < 6 * WSZ)           { src = W_f;   dst = WF;  off = i - 5 * WSZ; }
    else if (i < 6 * WSZ + ASZ)     { src = point; dst = P16; off = i - 6 * WSZ; }
    else                            { src = img;   dst = I16; off = i - 6 * WSZ - ASZ; }
    float4 v = *reinterpret_cast<const float4*>(src + off);
    __half2* d = reinterpret_cast<__half2*>(dst + off);
    d[0] = __floats2half2_rn(v.x, v.y);
    d[1] = __floats2half2_rn(v.z, v.w);
}

// ---------------- softmax over heads (32 blocks x 128) ----------------
__global__ __launch_bounds__(128) void softmax_heads(
    const float* __restrict__ partial, float* __restrict__ weight,
    float* __restrict__ wmap_out)
{
    int n = blockIdx.x * 128 + threadIdx.x;
    float s[NHEADS] = {0.f, 0.f, 0.f, 0.f};
    #pragma unroll
    for (int h = 0; h < NHEADS; h++)
        #pragma unroll
        for (int j = 0; j < NSCHUNK; j++)
            s[h] += partial[((size_t)(h * NSCHUNK + j)) * N_DIM + n];
    const float inv_sqrt_dk = 1.0f / 32.0f;
    float m = -1e30f;
    #pragma unroll
    for (int h = 0; h < NHEADS; h++) { s[h] *= inv_sqrt_dk; m = fmaxf(m, s[h]); }
    float e[NHEADS], sum = 0.f;
    #pragma unroll
    for (int h = 0; h < NHEADS; h++) { e[h] = __expf(s[h] - m); sum += e[h]; }
    float inv = 1.0f / sum;
    #pragma unroll
    for (int h = 0; h < NHEADS; h++) {
        float wv = e[h] * inv;
        weight[(size_t)h * N_DIM + n]   = wv;
        wmap_out[(size_t)h * N_DIM + n] = wv;
    }
}

// ---------------- z + residual + LayerNorm (16B loads: 8 n per thread) ----------------
__global__ __launch_bounds__(512) void z_layernorm(
    const __half* __restrict__ keysh, const __half* __restrict__ qh,
    const float* __restrict__ weight, const float* __restrict__ gamma,
    const float* __restrict__ beta, __half* __restrict__ fusedh)
{
    const int c = blockIdx.x;
    __shared__ float r1[16], r2[16];
    __shared__ float s_mean, s_rstd;

    const int n8 = threadIdx.x * 8;      // each thread owns 8 contiguous n (16B in fp16)
    float v[8];
    float lsum = 0.f, lsq = 0.f;
    {
        float4 qv4 = *reinterpret_cast<const float4*>(&qh[(size_t)c * N_DIM + n8]);
        const __half2* qp = reinterpret_cast<const __half2*>(&qv4);
        #pragma unroll
        for (int p = 0; p < 4; p++) {
            float2 f = __half22float2(qp[p]);
            v[p * 2 + 0] = f.x; v[p * 2 + 1] = f.y;
        }
        #pragma unroll
        for (int h = 0; h < NHEADS; h++) {
            float4 kv4 = *reinterpret_cast<const float4*>(
                &keysh[((size_t)(h * L_DIM + c)) * N_DIM + n8]);
            const __half2* kp = reinterpret_cast<const __half2*>(&kv4);
            float4 w0 = *reinterpret_cast<const float4*>(&weight[(size_t)h * N_DIM + n8]);
            float4 w1 = *reinterpret_cast<const float4*>(&weight[(size_t)h * N_DIM + n8 + 4]);
            const float* wp = &w0.x;
            float2 f0 = __half22float2(kp[0]);
            float2 f1 = __half22float2(kp[1]);
            float2 f2 = __half22float2(kp[2]);
            float2 f3 = __half22float2(kp[3]);
            v[0] += w0.x * f0.x; v[1] += w0.y * f0.y;
            v[2] += w0.z * f1.x; v[3] += w0.w * f1.y;
            v[4] += w1.x * f2.x; v[5] += w1.y * f2.y;
            v[6] += w1.z * f3.x; v[7] += w1.w * f3.y;
            (void)wp;
        }
        #pragma unroll
        for (int e = 0; e < 8; e++) { lsum += v[e]; lsq += v[e] * v[e]; }
    }
    #pragma unroll
    for (int o = 16; o > 0; o >>= 1) {
        lsum += __shfl_xor_sync(0xffffffffu, lsum, o);
        lsq  += __shfl_xor_sync(0xffffffffu, lsq, o);
    }
    const int wid = threadIdx.x >> 5, lid = threadIdx.x & 31;
    if (lid == 0) { r1[wid] = lsum; r2[wid] = lsq; }
    __syncthreads();
    if (threadIdx.x == 0) {
        float ts = 0.f, tq = 0.f;
        #pragma unroll
        for (int i = 0; i < 16; i++) { ts += r1[i]; tq += r2[i]; }
        float mean = ts * (1.0f / N_DIM);
        float var  = tq * (1.0f / N_DIM) - mean * mean;
        s_mean = mean;
        s_rstd = rsqrtf(var + 1e-5f);
    }
    __syncthreads();
    const float mean = s_mean, rstd = s_rstd;
    {
        float4 g0 = *reinterpret_cast<const float4*>(&gamma[n8]);
        float4 g1 = *reinterpret_cast<const float4*>(&gamma[n8 + 4]);
        float4 b0 = *reinterpret_cast<const float4*>(&beta[n8]);
        float4 b1 = *reinterpret_cast<const float4*>(&beta[n8 + 4]);
        float o[8];
        o[0] = (v[0] - mean) * rstd * g0.x + b0.x;
        o[1] = (v[1] - mean) * rstd * g0.y + b0.y;
        o[2] = (v[2] - mean) * rstd * g0.z + b0.z;
        o[3] = (v[3] - mean) * rstd * g0.w + b0.w;
        o[4] = (v[4] - mean) * rstd * g1.x + b1.x;
        o[5] = (v[5] - mean) * rstd * g1.y + b1.y;
        o[6] = (v[6] - mean) * rstd * g1.z + b1.z;
        o[7] = (v[7] - mean) * rstd * g1.w + b1.w;
        float4 pack;
        __half2* pp = reinterpret_cast<__half2*>(&pack);
        pp[0] = __floats2half2_rn(o[0], o[1]);
        pp[1] = __floats2half2_rn(o[2], o[3]);
        pp[2] = __floats2half2_rn(o[4], o[5]);
        pp[3] = __floats2half2_rn(o[6], o[7]);
        *reinterpret_cast<float4*>(&fusedh[(size_t)c * N_DIM + n8]) = pack;
    }
}

// ---------------- launch ----------------
extern "C" void kernel_launch(void* const* d_in, const int* in_sizes, int n_in,
                              void* d_out, int out_size)
{
    const float* point = (const float*)d_in[0];
    const float* img   = (const float*)d_in[1];
    const float* W_img = (const float*)d_in[2];
    const float* b_img = (const float*)d_in[3];
    const float* W_L   = (const float*)d_in[4];
    const float* b_L   = (const float*)d_in[5];
    const float* ln_g  = (const float*)d_in[6];
    const float* ln_b  = (const float*)d_in[7];
    const float* W_f   = (const float*)d_in[8];
    const float* b_f   = (const float*)d_in[9];

    float* out  = (float*)d_out;
    float* wmap = out + (size_t)L_DIM * N_DIM;

    float *partial, *weight;
    __half *qh, *keysh, *fusedh;
    cudaGetSymbolAddress((void**)&qh,      g_qh);
    cudaGetSymbolAddress((void**)&keysh,   g_keysh);
    cudaGetSymbolAddress((void**)&partial, g_partial);
    cudaGetSymbolAddress((void**)&weight,  g_weight);
    cudaGetSymbolAddress((void**)&fusedh,  g_fusedh);

    __half *WL, *WI, *WF, *P16, *I16;
    cudaGetSymbolAddress((void**)&WL, g_WL);
    cudaGetSymbolAddress((void**)&WI, g_Wimg);
    cudaGetSymbolAddress((void**)&WF, g_Wf);
    cudaGetSymbolAddress((void**)&P16, g_P16);
    cudaGetSymbolAddress((void**)&I16, g_I16);

    cudaFuncSetAttribute(gemm_q,    cudaFuncAttributeMaxDynamicSharedMemorySize, GEMM_DSMEM);
    cudaFuncSetAttribute(gemm_keys, cudaFuncAttributeMaxDynamicSharedMemorySize, GEMM_DSMEM);
    cudaFuncSetAttribute(gemm_f,    cudaFuncAttributeMaxDynamicSharedMemorySize, GEMM_DSMEM);

    convert_all<<<(14 * 1024 * 1024) / 1024, 256>>>(
        W_L, W_img, W_f, point, img, WL, WI, WF, P16, I16);

    gemm_q<<<dim3(N_DIM / GBN, L_DIM / GBM), 256, GEMM_DSMEM>>>(WL, P16, b_L, qh);
    gemm_keys<<<dim3(N_DIM / GBN, (NHEADS * L_DIM) / GBM), 256, GEMM_DSMEM>>>(
        WI, I16, b_img, keysh, qh, partial);

    softmax_heads<<<N_DIM / 128, 128>>>(partial, weight, wmap);
    z_layernorm<<<L_DIM, 512>>>(keysh, qh, weight, ln_g, ln_b, fusedh);

    gemm_f<<<dim3(N_DIM / GBN, L_DIM / GBM), 256, GEMM_DSMEM>>>(WF, fusedh, b_f, out);
}